// round 1
// baseline (speedup 1.0000x reference)
#include <cuda_runtime.h>
#include <math.h>

#define NN   250000
#define EE   1000000
#define BB   25
#define NX_  8
#define NY_  9
#define NCC  72
#define MM   1800
#define GRD  16
#define NOUTC 2
#define EPSB 1e-5f

// ---------------- scratch (device globals; no allocation allowed) -------------
__device__ float d_xA[NN * 32];          // conv outputs (post BN+relu)
__device__ float d_xB[NN * 32];          // conv accumulators / divided values
__device__ int   d_deg[NN];
__device__ int   d_clu[NN];
__device__ float d_stats[64];            // [sum(Cout), sumsq(Cout)]
__device__ float d_xp[MM * 32];          // pooled features (max pooled)
__device__ float d_pp[MM * 3];           // pooled positions
__device__ int   d_cnt[MM];
__device__ unsigned char d_adj[MM * MM];
__device__ int   d_maxv;                 // float bits (non-negative)
__device__ int   d_nm;                   // number of non-empty cells
__device__ float d_pz[MM * 8 * 32];      // per-node spline projections
__device__ float d_xt[MM * 32];          // pooled conv raw output
__device__ float d_xu[MM * 32];          // pooled conv post-BN output
__device__ float d_xg[BB * GRD * 32];    // MaxPoolingX output

// ---------------- helpers ----------------------------------------------------
__device__ __forceinline__ void basis8(float p0, float p1, float p2, float* b) {
    p0 = fminf(fmaxf(p0, 0.f), 1.f);
    p1 = fminf(fmaxf(p1, 0.f), 1.f);
    p2 = fminf(fmaxf(p2, 0.f), 1.f);
    float q0 = 1.f - p0, q1 = 1.f - p1, q2 = 1.f - p2;
    b[0] = q0 * q1 * q2; b[1] = p0 * q1 * q2;
    b[2] = q0 * p1 * q2; b[3] = p0 * p1 * q2;
    b[4] = q0 * q1 * p2; b[5] = p0 * q1 * p2;
    b[6] = q0 * p1 * p2; b[7] = p0 * p1 * p2;
}

__device__ __forceinline__ void atomicMaxFloatPos(float* addr, float v) {
    // valid for v >= 0 with 0-initialized destination
    atomicMax(reinterpret_cast<int*>(addr), __float_as_int(v));
}

// ---------------- degree -----------------------------------------------------
__global__ void k_deg(const int* __restrict__ dst) {
    int e = blockIdx.x * blockDim.x + threadIdx.x;
    if (e < EE) atomicAdd(&d_deg[dst[e]], 1);
}

// ---------------- SplineConv edge scatter ------------------------------------
template <int CIN, int COUT>
__global__ void k_edge(const float* __restrict__ xin, const float* __restrict__ W,
                       const int* __restrict__ src, const int* __restrict__ dst,
                       const float* __restrict__ ea) {
    __shared__ float Wsh[8 * CIN * COUT];
    for (int i = threadIdx.x; i < 8 * CIN * COUT; i += blockDim.x) Wsh[i] = W[i];
    __syncthreads();
    int e = blockIdx.x * blockDim.x + threadIdx.x;
    if (e >= EE) return;
    int s = src[e], d = dst[e];
    float bs[8];
    basis8(ea[3 * e + 0], ea[3 * e + 1], ea[3 * e + 2], bs);
    float xs[CIN];
    if constexpr (CIN % 4 == 0) {
        const float4* p = reinterpret_cast<const float4*>(xin + (size_t)s * CIN);
#pragma unroll
        for (int i = 0; i < CIN / 4; i++) {
            float4 v = p[i];
            xs[4 * i + 0] = v.x; xs[4 * i + 1] = v.y;
            xs[4 * i + 2] = v.z; xs[4 * i + 3] = v.w;
        }
    } else {
#pragma unroll
        for (int i = 0; i < CIN; i++) xs[i] = xin[(size_t)s * CIN + i];
    }
    float acc[COUT];
#pragma unroll
    for (int c = 0; c < COUT; c++) acc[c] = 0.f;
#pragma unroll
    for (int k = 0; k < 8; k++) {
#pragma unroll
        for (int ci = 0; ci < CIN; ci++) {
            float t = bs[k] * xs[ci];
            const float* wp = &Wsh[(k * CIN + ci) * COUT];
#pragma unroll
            for (int co = 0; co < COUT; co++) acc[co] += t * wp[co];
        }
    }
    float* op = &d_xB[(size_t)d * COUT];
#pragma unroll
    for (int co = 0; co < COUT; co++) atomicAdd(&op[co], acc[co]);
}

// ---------------- mean-divide + BN stats -------------------------------------
template <int COUT>
__global__ void k_div_stats() {
    const int T = gridDim.x * blockDim.x;
    int t = blockIdx.x * blockDim.x + threadIdx.x;
    const int c = t % COUT;  // constant per thread (T % COUT == 0)
    float sum = 0.f, sq = 0.f;
    for (int i = t; i < NN * COUT; i += T) {
        int n = i / COUT;
        float v = d_xB[i] / fmaxf((float)d_deg[n], 1.f);
        d_xB[i] = v;
        sum += v; sq += v * v;
    }
    __shared__ float ss[COUT], s2[COUT];
    if (threadIdx.x < COUT) { ss[threadIdx.x] = 0.f; s2[threadIdx.x] = 0.f; }
    __syncthreads();
    atomicAdd(&ss[c], sum);
    atomicAdd(&s2[c], sq);
    __syncthreads();
    if (threadIdx.x < COUT) {
        atomicAdd(&d_stats[threadIdx.x], ss[threadIdx.x]);
        atomicAdd(&d_stats[COUT + threadIdx.x], s2[threadIdx.x]);
    }
}

// ---------------- BN finalize + relu -----------------------------------------
template <int COUT>
__global__ void k_bn(const float* __restrict__ g, const float* __restrict__ b) {
    const int T = gridDim.x * blockDim.x;
    int t = blockIdx.x * blockDim.x + threadIdx.x;
    const int c = t % COUT;
    float mean = d_stats[c] * (1.f / NN);
    float var = d_stats[COUT + c] * (1.f / NN) - mean * mean;
    float sc = rsqrtf(var + EPSB) * g[c];
    float sh = b[c] - mean * sc;
    for (int i = t; i < NN * COUT; i += T) {
        float v = d_xB[i] * sc + sh;
        d_xA[i] = fmaxf(v, 0.f);
    }
}

// ---------------- voxel pooling ----------------------------------------------
__global__ void k_cluster(const float* __restrict__ pos, const int* __restrict__ batch,
                          const float* __restrict__ x) {
    int n = blockIdx.x * blockDim.x + threadIdx.x;
    if (n >= NN) return;
    float p0 = pos[3 * n + 0], p1 = pos[3 * n + 1], p2 = pos[3 * n + 2];
    int cx = min(max((int)floorf(p0 / 16.0f), 0), NX_ - 1);
    int cy = min(max((int)floorf(p1 / 12.0f), 0), NY_ - 1);
    int cl = batch[n] * NCC + cy * NX_ + cx;
    d_clu[n] = cl;
    atomicAdd(&d_cnt[cl], 1);
    atomicAdd(&d_pp[cl * 3 + 0], p0);
    atomicAdd(&d_pp[cl * 3 + 1], p1);
    atomicAdd(&d_pp[cl * 3 + 2], p2);
    const float4* xr = reinterpret_cast<const float4*>(x + (size_t)n * 32);
#pragma unroll
    for (int i = 0; i < 8; i++) {
        float4 v = xr[i];
        atomicMaxFloatPos(&d_xp[cl * 32 + 4 * i + 0], v.x);
        atomicMaxFloatPos(&d_xp[cl * 32 + 4 * i + 1], v.y);
        atomicMaxFloatPos(&d_xp[cl * 32 + 4 * i + 2], v.z);
        atomicMaxFloatPos(&d_xp[cl * 32 + 4 * i + 3], v.w);
    }
}

__global__ void k_ppfin() {
    int m = blockIdx.x * blockDim.x + threadIdx.x;
    if (m >= MM) return;
    float c = fmaxf((float)d_cnt[m], 1.f);
    d_pp[m * 3 + 0] /= c;
    d_pp[m * 3 + 1] /= c;
    d_pp[m * 3 + 2] /= c;
    if (d_cnt[m] > 0) atomicAdd(&d_nm, 1);
}

__global__ void k_adj(const int* __restrict__ src, const int* __restrict__ dst) {
    int e = blockIdx.x * blockDim.x + threadIdx.x;
    if (e >= EE) return;
    int a = d_clu[src[e]], b = d_clu[dst[e]];
    if (a != b) d_adj[a * MM + b] = 1;
}

__global__ void k_maxv() {
    const int T = gridDim.x * blockDim.x;
    int t = blockIdx.x * blockDim.x + threadIdx.x;
    float mx = 0.f;
    for (int p = t; p < MM * MM; p += T) {
        if (d_adj[p]) {
            int r = p / MM, c = p % MM;
            mx = fmaxf(mx, fabsf(d_pp[c * 3 + 0] - d_pp[r * 3 + 0]));
            mx = fmaxf(mx, fabsf(d_pp[c * 3 + 1] - d_pp[r * 3 + 1]));
            mx = fmaxf(mx, fabsf(d_pp[c * 3 + 2] - d_pp[r * 3 + 2]));
        }
    }
    __shared__ float red[256];
    red[threadIdx.x] = mx;
    __syncthreads();
    for (int o = 128; o > 0; o >>= 1) {
        if (threadIdx.x < o) red[threadIdx.x] = fmaxf(red[threadIdx.x], red[threadIdx.x + o]);
        __syncthreads();
    }
    if (threadIdx.x == 0) atomicMax(&d_maxv, __float_as_int(red[0]));
}

// ---------------- pooled conv: per-node projections z = x . W[s] --------------
__global__ void k_pz(const float* __restrict__ xin, const float* __restrict__ W) {
    int t = blockIdx.x * blockDim.x + threadIdx.x;
    if (t >= MM * 8 * 32) return;
    int co = t & 31;
    int s = (t >> 5) & 7;
    int r = t >> 8;
    float acc = 0.f;
    const float* xr = &xin[r * 32];
    const float* wp = &W[s * 32 * 32 + co];
#pragma unroll
    for (int ci = 0; ci < 32; ci++) acc += xr[ci] * wp[ci * 32];
    d_pz[t] = acc;
}

// ---------------- pooled conv: per-dst aggregation ---------------------------
__global__ void k_pconv(float* __restrict__ out) {
    int c = blockIdx.x;
    int lane = threadIdx.x & 31;
    int w = threadIdx.x >> 5;  // 8 warps
    int g = c / NCC;
    int base = g * NCC;
    float inv = 0.5f / fmaxf(__int_as_float(d_maxv), 1e-9f);
    float pc0 = d_pp[c * 3 + 0], pc1 = d_pp[c * 3 + 1], pc2 = d_pp[c * 3 + 2];
    float acc = 0.f;
    int cnt = 0;
    for (int r = base + w; r < base + NCC; r += 8) {
        if (r == c || !d_adj[r * MM + c]) continue;
        cnt++;
        float bs[8];
        basis8((pc0 - d_pp[r * 3 + 0]) * inv + 0.5f,
               (pc1 - d_pp[r * 3 + 1]) * inv + 0.5f,
               (pc2 - d_pp[r * 3 + 2]) * inv + 0.5f, bs);
        const float* z = &d_pz[r * 256];
#pragma unroll
        for (int s = 0; s < 8; s++) acc += bs[s] * z[s * 32 + lane];
    }
    __shared__ float sa[8][32];
    __shared__ int scn[8];
    sa[w][lane] = acc;
    if (lane == 0) scn[w] = cnt;
    __syncthreads();
    if (w == 0) {
        float a = 0.f;
        int k = 0;
#pragma unroll
        for (int j = 0; j < 8; j++) { a += sa[j][lane]; k += scn[j]; }
        out[c * 32 + lane] = a / fmaxf((float)k, 1.f);
    }
}

// ---------------- pooled (masked) BN stats + finalize ------------------------
__global__ void k_pstats(const float* __restrict__ x) {
    int tid = threadIdx.x;  // one block, 1024 threads
    const int c = tid & 31;
    float sum = 0.f, sq = 0.f;
    for (int i = tid; i < MM * 32; i += 1024) {
        if (d_cnt[i >> 5] > 0) {
            float v = x[i];
            sum += v; sq += v * v;
        }
    }
    __shared__ float ss[32], s2[32];
    if (tid < 32) { ss[tid] = 0.f; s2[tid] = 0.f; }
    __syncthreads();
    atomicAdd(&ss[c], sum);
    atomicAdd(&s2[c], sq);
    __syncthreads();
    if (tid < 32) { d_stats[tid] = ss[tid]; d_stats[32 + tid] = s2[tid]; }
}

__global__ void k_pbn(const float* __restrict__ x, const float* __restrict__ g,
                      const float* __restrict__ b, float* __restrict__ out) {
    int i = blockIdx.x * blockDim.x + threadIdx.x;
    if (i >= MM * 32) return;
    int c = i & 31;
    float cntf = fmaxf((float)d_nm, 1.f);
    float mean = d_stats[c] / cntf;
    float var = d_stats[32 + c] / cntf - mean * mean;
    float v = (x[i] - mean) * rsqrtf(var + EPSB) * g[c] + b[c];
    if (d_cnt[i >> 5] <= 0) v = 0.f;
    out[i] = fmaxf(v, 0.f);
}

// ---------------- MaxPoolingX + FC -------------------------------------------
__global__ void k_poolX(const float* __restrict__ x) {
    int i = blockIdx.x * blockDim.x + threadIdx.x;
    if (i >= MM * 32) return;
    int m = i >> 5, ch = i & 31;
    if (d_cnt[m] <= 0) return;
    int g = m / NCC;
    int gx = min(max((int)floorf(d_pp[m * 3 + 0] / 30.0f), 0), 3);
    int gy = min(max((int)floorf(d_pp[m * 3 + 1] / 25.0f), 0), 3);
    int seg = g * GRD + gy * 4 + gx;
    atomicMaxFloatPos(&d_xg[seg * 32 + ch], x[i]);
}

__global__ void k_fc(const float* __restrict__ fcw, float* __restrict__ out) {
    int b = blockIdx.x;            // BB blocks
    int o = threadIdx.x >> 5;      // 2 warps
    int lane = threadIdx.x & 31;
    float s = 0.f;
    for (int j = lane; j < GRD * 32; j += 32)
        s += d_xg[b * GRD * 32 + j] * fcw[o * GRD * 32 + j];
#pragma unroll
    for (int off = 16; off; off >>= 1) s += __shfl_down_sync(0xffffffff, s, off);
    if (lane == 0) out[b * NOUTC + o] = s;
}

// ---------------- host orchestration -----------------------------------------
extern "C" void kernel_launch(void* const* d_in, const int* in_sizes, int n_in,
                              void* d_out, int out_size) {
    const float* x   = (const float*)d_in[0];
    const float* pos = (const float*)d_in[1];
    const float* ea  = (const float*)d_in[2];
    const float* w[7];
    const float* gm[7];
    const float* bt[7];
    for (int i = 0; i < 7; i++) {
        w[i]  = (const float*)d_in[3 + i];
        gm[i] = (const float*)d_in[10 + i];
        bt[i] = (const float*)d_in[17 + i];
    }
    const float* fcw = (const float*)d_in[24];
    const int* ei    = (const int*)d_in[25];
    const int* batch = (const int*)d_in[26];
    const int* src = ei;
    const int* dst = ei + EE;
    float* out = (float*)d_out;

    void *pxA, *pxB, *pdeg, *pstats, *pxp, *ppp, *pcnt, *padj, *pmaxv, *pnm, *pxg, *pxu;
    cudaGetSymbolAddress(&pxA, d_xA);
    cudaGetSymbolAddress(&pxB, d_xB);
    cudaGetSymbolAddress(&pdeg, d_deg);
    cudaGetSymbolAddress(&pstats, d_stats);
    cudaGetSymbolAddress(&pxp, d_xp);
    cudaGetSymbolAddress(&ppp, d_pp);
    cudaGetSymbolAddress(&pcnt, d_cnt);
    cudaGetSymbolAddress(&padj, d_adj);
    cudaGetSymbolAddress(&pmaxv, d_maxv);
    cudaGetSymbolAddress(&pnm, d_nm);
    cudaGetSymbolAddress(&pxg, d_xg);
    cudaGetSymbolAddress(&pxu, d_xu);

    const int TB = 256;
    const int EG = (EE + TB - 1) / TB;
    const int NG = (NN + TB - 1) / TB;

    cudaMemsetAsync(pdeg, 0, (size_t)NN * 4, 0);
    k_deg<<<EG, TB>>>(dst);

    // conv1: 1 -> 8
    cudaMemsetAsync(pxB, 0, (size_t)NN * 8 * 4, 0);
    k_edge<1, 8><<<EG, TB>>>(x, w[0], src, dst, ea);
    cudaMemsetAsync(pstats, 0, 64 * 4, 0);
    k_div_stats<8><<<592, TB>>>();
    k_bn<8><<<592, TB>>>(gm[0], bt[0]);

    // conv2: 8 -> 16
    cudaMemsetAsync(pxB, 0, (size_t)NN * 16 * 4, 0);
    k_edge<8, 16><<<EG, TB>>>((const float*)pxA, w[1], src, dst, ea);
    cudaMemsetAsync(pstats, 0, 64 * 4, 0);
    k_div_stats<16><<<592, TB>>>();
    k_bn<16><<<592, TB>>>(gm[1], bt[1]);

    // conv3: 16 -> 16
    cudaMemsetAsync(pxB, 0, (size_t)NN * 16 * 4, 0);
    k_edge<16, 16><<<EG, TB>>>((const float*)pxA, w[2], src, dst, ea);
    cudaMemsetAsync(pstats, 0, 64 * 4, 0);
    k_div_stats<16><<<592, TB>>>();
    k_bn<16><<<592, TB>>>(gm[2], bt[2]);

    // conv4: 16 -> 16
    cudaMemsetAsync(pxB, 0, (size_t)NN * 16 * 4, 0);
    k_edge<16, 16><<<EG, TB>>>((const float*)pxA, w[3], src, dst, ea);
    cudaMemsetAsync(pstats, 0, 64 * 4, 0);
    k_div_stats<16><<<592, TB>>>();
    k_bn<16><<<592, TB>>>(gm[3], bt[3]);

    // conv5: 16 -> 32
    cudaMemsetAsync(pxB, 0, (size_t)NN * 32 * 4, 0);
    k_edge<16, 32><<<EG, TB>>>((const float*)pxA, w[4], src, dst, ea);
    cudaMemsetAsync(pstats, 0, 64 * 4, 0);
    k_div_stats<32><<<592, TB>>>();
    k_bn<32><<<592, TB>>>(gm[4], bt[4]);

    // ---- MaxPooling (voxel grid) ----
    cudaMemsetAsync(pxp, 0, (size_t)MM * 32 * 4, 0);
    cudaMemsetAsync(ppp, 0, (size_t)MM * 3 * 4, 0);
    cudaMemsetAsync(pcnt, 0, (size_t)MM * 4, 0);
    cudaMemsetAsync(padj, 0, (size_t)MM * MM, 0);
    cudaMemsetAsync(pmaxv, 0, 4, 0);
    cudaMemsetAsync(pnm, 0, 4, 0);
    cudaMemsetAsync(pxg, 0, (size_t)BB * GRD * 32 * 4, 0);

    k_cluster<<<NG, TB>>>(pos, batch, (const float*)pxA);
    k_ppfin<<<(MM + TB - 1) / TB, TB>>>();
    k_adj<<<EG, TB>>>(src, dst);
    k_maxv<<<592, TB>>>();

    // conv6: 32 -> 32 (pooled)
    k_pz<<<(MM * 256 + TB - 1) / TB, TB>>>((const float*)pxp, w[5]);
    k_pconv<<<MM, 256>>>(d_xt);
    k_pstats<<<1, 1024>>>(d_xt);
    k_pbn<<<(MM * 32 + TB - 1) / TB, TB>>>(d_xt, gm[5], bt[5], (float*)pxu);

    // conv7: 32 -> 32 (pooled)
    k_pz<<<(MM * 256 + TB - 1) / TB, TB>>>((const float*)pxu, w[6]);
    k_pconv<<<MM, 256>>>(d_xt);
    k_pstats<<<1, 1024>>>(d_xt);
    k_pbn<<<(MM * 32 + TB - 1) / TB, TB>>>(d_xt, gm[6], bt[6], (float*)pxu);

    // ---- MaxPoolingX + FC ----
    k_poolX<<<(MM * 32 + TB - 1) / TB, TB>>>((const float*)pxu);
    k_fc<<<BB, 64>>>(fcw, out);
}

// round 2
// speedup vs baseline: 1.0039x; 1.0039x over previous
#include <cuda_runtime.h>
#include <math.h>

#define NN   250000
#define EE   1000000
#define BB   25
#define NX_  8
#define NY_  9
#define NCC  72
#define MM   1800
#define GRD  16
#define NOUTC 2
#define EPSB 1e-5f

// ---------------- scratch (device globals; no allocation allowed) -------------
__device__ float d_xA[NN * 32];          // conv outputs (post BN+relu)
__device__ float d_xB[NN * 32];          // conv accumulators / divided values
__device__ int   d_deg[NN];
__device__ int   d_clu[NN];
__device__ float d_stats[64];            // [sum(Cout), sumsq(Cout)]
__device__ float d_xp[MM * 32];          // pooled features (max pooled)
__device__ float d_pp[MM * 3];           // pooled positions
__device__ int   d_cnt[MM];
__device__ unsigned char d_adj[MM * MM];
__device__ int   d_maxv;                 // float bits (non-negative)
__device__ int   d_nm;                   // number of non-empty cells
__device__ float d_pz[MM * 8 * 32];      // per-node spline projections
__device__ float d_xt[MM * 32];          // pooled conv raw output
__device__ float d_xu[MM * 32];          // pooled conv post-BN output
__device__ float d_xg[BB * GRD * 32];    // MaxPoolingX output

// ---------------- helpers ----------------------------------------------------
__device__ __forceinline__ void basis8(float p0, float p1, float p2, float* b) {
    p0 = fminf(fmaxf(p0, 0.f), 1.f);
    p1 = fminf(fmaxf(p1, 0.f), 1.f);
    p2 = fminf(fmaxf(p2, 0.f), 1.f);
    float q0 = 1.f - p0, q1 = 1.f - p1, q2 = 1.f - p2;
    b[0] = q0 * q1 * q2; b[1] = p0 * q1 * q2;
    b[2] = q0 * p1 * q2; b[3] = p0 * p1 * q2;
    b[4] = q0 * q1 * p2; b[5] = p0 * q1 * p2;
    b[6] = q0 * p1 * p2; b[7] = p0 * p1 * p2;
}

__device__ __forceinline__ void atomicMaxFloatPos(float* addr, float v) {
    // valid for v >= 0 with 0-initialized destination
    atomicMax(reinterpret_cast<int*>(addr), __float_as_int(v));
}

// ---------------- degree -----------------------------------------------------
__global__ void k_deg(const int* __restrict__ dst) {
    int e = blockIdx.x * blockDim.x + threadIdx.x;
    if (e < EE) atomicAdd(&d_deg[dst[e]], 1);
}

// ---------------- SplineConv edge scatter ------------------------------------
template <int CIN, int COUT>
__global__ void k_edge(const float* __restrict__ xin, const float* __restrict__ W,
                       const int* __restrict__ src, const int* __restrict__ dst,
                       const float* __restrict__ ea) {
    __shared__ float Wsh[8 * CIN * COUT];
    for (int i = threadIdx.x; i < 8 * CIN * COUT; i += blockDim.x) Wsh[i] = W[i];
    __syncthreads();
    int e = blockIdx.x * blockDim.x + threadIdx.x;
    if (e >= EE) return;
    int s = src[e], d = dst[e];
    float bs[8];
    basis8(ea[3 * e + 0], ea[3 * e + 1], ea[3 * e + 2], bs);
    float xs[CIN];
    if constexpr (CIN % 4 == 0) {
        const float4* p = reinterpret_cast<const float4*>(xin + (size_t)s * CIN);
#pragma unroll
        for (int i = 0; i < CIN / 4; i++) {
            float4 v = p[i];
            xs[4 * i + 0] = v.x; xs[4 * i + 1] = v.y;
            xs[4 * i + 2] = v.z; xs[4 * i + 3] = v.w;
        }
    } else {
#pragma unroll
        for (int i = 0; i < CIN; i++) xs[i] = xin[(size_t)s * CIN + i];
    }
    float acc[COUT];
#pragma unroll
    for (int c = 0; c < COUT; c++) acc[c] = 0.f;
#pragma unroll
    for (int k = 0; k < 8; k++) {
#pragma unroll
        for (int ci = 0; ci < CIN; ci++) {
            float t = bs[k] * xs[ci];
            const float* wp = &Wsh[(k * CIN + ci) * COUT];
#pragma unroll
            for (int co = 0; co < COUT; co++) acc[co] += t * wp[co];
        }
    }
    float* op = &d_xB[(size_t)d * COUT];
#pragma unroll
    for (int co = 0; co < COUT; co++) atomicAdd(&op[co], acc[co]);
}

// ---------------- mean-divide + BN stats -------------------------------------
template <int COUT>
__global__ void k_div_stats() {
    const int T = gridDim.x * blockDim.x;
    int t = blockIdx.x * blockDim.x + threadIdx.x;
    const int c = t % COUT;  // constant per thread (T % COUT == 0)
    float sum = 0.f, sq = 0.f;
    for (int i = t; i < NN * COUT; i += T) {
        int n = i / COUT;
        float v = d_xB[i] / fmaxf((float)d_deg[n], 1.f);
        d_xB[i] = v;
        sum += v; sq += v * v;
    }
    __shared__ float ss[COUT], s2[COUT];
    if (threadIdx.x < COUT) { ss[threadIdx.x] = 0.f; s2[threadIdx.x] = 0.f; }
    __syncthreads();
    atomicAdd(&ss[c], sum);
    atomicAdd(&s2[c], sq);
    __syncthreads();
    if (threadIdx.x < COUT) {
        atomicAdd(&d_stats[threadIdx.x], ss[threadIdx.x]);
        atomicAdd(&d_stats[COUT + threadIdx.x], s2[threadIdx.x]);
    }
}

// ---------------- BN finalize + relu -----------------------------------------
template <int COUT>
__global__ void k_bn(const float* __restrict__ g, const float* __restrict__ b) {
    const int T = gridDim.x * blockDim.x;
    int t = blockIdx.x * blockDim.x + threadIdx.x;
    const int c = t % COUT;
    float mean = d_stats[c] * (1.f / NN);
    float var = d_stats[COUT + c] * (1.f / NN) - mean * mean;
    float sc = rsqrtf(var + EPSB) * g[c];
    float sh = b[c] - mean * sc;
    for (int i = t; i < NN * COUT; i += T) {
        float v = d_xB[i] * sc + sh;
        d_xA[i] = fmaxf(v, 0.f);
    }
}

// ---------------- voxel pooling ----------------------------------------------
__global__ void k_cluster(const float* __restrict__ pos, const int* __restrict__ batch,
                          const float* __restrict__ x) {
    int n = blockIdx.x * blockDim.x + threadIdx.x;
    if (n >= NN) return;
    float p0 = pos[3 * n + 0], p1 = pos[3 * n + 1], p2 = pos[3 * n + 2];
    int cx = min(max((int)floorf(p0 / 16.0f), 0), NX_ - 1);
    int cy = min(max((int)floorf(p1 / 12.0f), 0), NY_ - 1);
    int cl = batch[n] * NCC + cy * NX_ + cx;
    d_clu[n] = cl;
    atomicAdd(&d_cnt[cl], 1);
    atomicAdd(&d_pp[cl * 3 + 0], p0);
    atomicAdd(&d_pp[cl * 3 + 1], p1);
    atomicAdd(&d_pp[cl * 3 + 2], p2);
    const float4* xr = reinterpret_cast<const float4*>(x + (size_t)n * 32);
#pragma unroll
    for (int i = 0; i < 8; i++) {
        float4 v = xr[i];
        atomicMaxFloatPos(&d_xp[cl * 32 + 4 * i + 0], v.x);
        atomicMaxFloatPos(&d_xp[cl * 32 + 4 * i + 1], v.y);
        atomicMaxFloatPos(&d_xp[cl * 32 + 4 * i + 2], v.z);
        atomicMaxFloatPos(&d_xp[cl * 32 + 4 * i + 3], v.w);
    }
}

__global__ void k_ppfin() {
    int m = blockIdx.x * blockDim.x + threadIdx.x;
    if (m >= MM) return;
    float c = fmaxf((float)d_cnt[m], 1.f);
    d_pp[m * 3 + 0] /= c;
    d_pp[m * 3 + 1] /= c;
    d_pp[m * 3 + 2] /= c;
    if (d_cnt[m] > 0) atomicAdd(&d_nm, 1);
}

__global__ void k_adj(const int* __restrict__ src, const int* __restrict__ dst) {
    int e = blockIdx.x * blockDim.x + threadIdx.x;
    if (e >= EE) return;
    int a = d_clu[src[e]], b = d_clu[dst[e]];
    if (a != b) d_adj[a * MM + b] = 1;
}

__global__ void k_maxv() {
    const int T = gridDim.x * blockDim.x;
    int t = blockIdx.x * blockDim.x + threadIdx.x;
    float mx = 0.f;
    for (int p = t; p < MM * MM; p += T) {
        if (d_adj[p]) {
            int r = p / MM, c = p % MM;
            mx = fmaxf(mx, fabsf(d_pp[c * 3 + 0] - d_pp[r * 3 + 0]));
            mx = fmaxf(mx, fabsf(d_pp[c * 3 + 1] - d_pp[r * 3 + 1]));
            mx = fmaxf(mx, fabsf(d_pp[c * 3 + 2] - d_pp[r * 3 + 2]));
        }
    }
    __shared__ float red[256];
    red[threadIdx.x] = mx;
    __syncthreads();
    for (int o = 128; o > 0; o >>= 1) {
        if (threadIdx.x < o) red[threadIdx.x] = fmaxf(red[threadIdx.x], red[threadIdx.x + o]);
        __syncthreads();
    }
    if (threadIdx.x == 0) atomicMax(&d_maxv, __float_as_int(red[0]));
}

// ---------------- pooled conv: per-node projections z = x . W[s] --------------
__global__ void k_pz(const float* __restrict__ xin, const float* __restrict__ W) {
    int t = blockIdx.x * blockDim.x + threadIdx.x;
    if (t >= MM * 8 * 32) return;
    int co = t & 31;
    int s = (t >> 5) & 7;
    int r = t >> 8;
    float acc = 0.f;
    const float* xr = &xin[r * 32];
    const float* wp = &W[s * 32 * 32 + co];
#pragma unroll
    for (int ci = 0; ci < 32; ci++) acc += xr[ci] * wp[ci * 32];
    d_pz[t] = acc;
}

// ---------------- pooled conv: per-dst aggregation ---------------------------
__global__ void k_pconv(float* __restrict__ out) {
    int c = blockIdx.x;
    int lane = threadIdx.x & 31;
    int w = threadIdx.x >> 5;  // 8 warps
    int g = c / NCC;
    int base = g * NCC;
    float inv = 0.5f / fmaxf(__int_as_float(d_maxv), 1e-9f);
    float pc0 = d_pp[c * 3 + 0], pc1 = d_pp[c * 3 + 1], pc2 = d_pp[c * 3 + 2];
    float acc = 0.f;
    int cnt = 0;
    for (int r = base + w; r < base + NCC; r += 8) {
        if (r == c || !d_adj[r * MM + c]) continue;
        cnt++;
        float bs[8];
        basis8((pc0 - d_pp[r * 3 + 0]) * inv + 0.5f,
               (pc1 - d_pp[r * 3 + 1]) * inv + 0.5f,
               (pc2 - d_pp[r * 3 + 2]) * inv + 0.5f, bs);
        const float* z = &d_pz[r * 256];
#pragma unroll
        for (int s = 0; s < 8; s++) acc += bs[s] * z[s * 32 + lane];
    }
    __shared__ float sa[8][32];
    __shared__ int scn[8];
    sa[w][lane] = acc;
    if (lane == 0) scn[w] = cnt;
    __syncthreads();
    if (w == 0) {
        float a = 0.f;
        int k = 0;
#pragma unroll
        for (int j = 0; j < 8; j++) { a += sa[j][lane]; k += scn[j]; }
        out[c * 32 + lane] = a / fmaxf((float)k, 1.f);
    }
}

// ---------------- pooled (masked) BN stats + finalize ------------------------
__global__ void k_pstats(const float* __restrict__ x) {
    int tid = threadIdx.x;  // one block, 1024 threads
    const int c = tid & 31;
    float sum = 0.f, sq = 0.f;
    for (int i = tid; i < MM * 32; i += 1024) {
        if (d_cnt[i >> 5] > 0) {
            float v = x[i];
            sum += v; sq += v * v;
        }
    }
    __shared__ float ss[32], s2[32];
    if (tid < 32) { ss[tid] = 0.f; s2[tid] = 0.f; }
    __syncthreads();
    atomicAdd(&ss[c], sum);
    atomicAdd(&s2[c], sq);
    __syncthreads();
    if (tid < 32) { d_stats[tid] = ss[tid]; d_stats[32 + tid] = s2[tid]; }
}

__global__ void k_pbn(const float* __restrict__ x, const float* __restrict__ g,
                      const float* __restrict__ b, float* __restrict__ out) {
    int i = blockIdx.x * blockDim.x + threadIdx.x;
    if (i >= MM * 32) return;
    int c = i & 31;
    float cntf = fmaxf((float)d_nm, 1.f);
    float mean = d_stats[c] / cntf;
    float var = d_stats[32 + c] / cntf - mean * mean;
    float v = (x[i] - mean) * rsqrtf(var + EPSB) * g[c] + b[c];
    if (d_cnt[i >> 5] <= 0) v = 0.f;
    out[i] = fmaxf(v, 0.f);
}

// ---------------- MaxPoolingX + FC -------------------------------------------
__global__ void k_poolX(const float* __restrict__ x) {
    int i = blockIdx.x * blockDim.x + threadIdx.x;
    if (i >= MM * 32) return;
    int m = i >> 5, ch = i & 31;
    if (d_cnt[m] <= 0) return;
    int g = m / NCC;
    int gx = min(max((int)floorf(d_pp[m * 3 + 0] / 30.0f), 0), 3);
    int gy = min(max((int)floorf(d_pp[m * 3 + 1] / 25.0f), 0), 3);
    int seg = g * GRD + gy * 4 + gx;
    atomicMaxFloatPos(&d_xg[seg * 32 + ch], x[i]);
}

__global__ void k_fc(const float* __restrict__ fcw, float* __restrict__ out) {
    int b = blockIdx.x;            // BB blocks
    int o = threadIdx.x >> 5;      // 2 warps
    int lane = threadIdx.x & 31;
    float s = 0.f;
    for (int j = lane; j < GRD * 32; j += 32)
        s += d_xg[b * GRD * 32 + j] * fcw[o * GRD * 32 + j];
#pragma unroll
    for (int off = 16; off; off >>= 1) s += __shfl_down_sync(0xffffffff, s, off);
    if (lane == 0) out[b * NOUTC + o] = s;
}

// ---------------- host orchestration -----------------------------------------
extern "C" void kernel_launch(void* const* d_in, const int* in_sizes, int n_in,
                              void* d_out, int out_size) {
    const float* x   = (const float*)d_in[0];
    const float* pos = (const float*)d_in[1];
    const float* ea  = (const float*)d_in[2];
    const float* w[7];
    const float* gm[7];
    const float* bt[7];
    for (int i = 0; i < 7; i++) {
        w[i]  = (const float*)d_in[3 + i];
        gm[i] = (const float*)d_in[10 + i];
        bt[i] = (const float*)d_in[17 + i];
    }
    const float* fcw = (const float*)d_in[24];
    const int* ei    = (const int*)d_in[25];
    const int* batch = (const int*)d_in[26];
    const int* src = ei;
    const int* dst = ei + EE;
    float* out = (float*)d_out;

    void *pxA, *pxB, *pdeg, *pstats, *pxp, *ppp, *pcnt, *padj, *pmaxv, *pnm, *pxg, *pxu;
    cudaGetSymbolAddress(&pxA, d_xA);
    cudaGetSymbolAddress(&pxB, d_xB);
    cudaGetSymbolAddress(&pdeg, d_deg);
    cudaGetSymbolAddress(&pstats, d_stats);
    cudaGetSymbolAddress(&pxp, d_xp);
    cudaGetSymbolAddress(&ppp, d_pp);
    cudaGetSymbolAddress(&pcnt, d_cnt);
    cudaGetSymbolAddress(&padj, d_adj);
    cudaGetSymbolAddress(&pmaxv, d_maxv);
    cudaGetSymbolAddress(&pnm, d_nm);
    cudaGetSymbolAddress(&pxg, d_xg);
    cudaGetSymbolAddress(&pxu, d_xu);

    const int TB = 256;
    const int EG = (EE + TB - 1) / TB;
    const int NG = (NN + TB - 1) / TB;

    cudaMemsetAsync(pdeg, 0, (size_t)NN * 4, 0);
    k_deg<<<EG, TB>>>(dst);

    // conv1: 1 -> 8
    cudaMemsetAsync(pxB, 0, (size_t)NN * 8 * 4, 0);
    k_edge<1, 8><<<EG, TB>>>(x, w[0], src, dst, ea);
    cudaMemsetAsync(pstats, 0, 64 * 4, 0);
    k_div_stats<8><<<592, TB>>>();
    k_bn<8><<<592, TB>>>(gm[0], bt[0]);

    // conv2: 8 -> 16
    cudaMemsetAsync(pxB, 0, (size_t)NN * 16 * 4, 0);
    k_edge<8, 16><<<EG, TB>>>((const float*)pxA, w[1], src, dst, ea);
    cudaMemsetAsync(pstats, 0, 64 * 4, 0);
    k_div_stats<16><<<592, TB>>>();
    k_bn<16><<<592, TB>>>(gm[1], bt[1]);

    // conv3: 16 -> 16
    cudaMemsetAsync(pxB, 0, (size_t)NN * 16 * 4, 0);
    k_edge<16, 16><<<EG, TB>>>((const float*)pxA, w[2], src, dst, ea);
    cudaMemsetAsync(pstats, 0, 64 * 4, 0);
    k_div_stats<16><<<592, TB>>>();
    k_bn<16><<<592, TB>>>(gm[2], bt[2]);

    // conv4: 16 -> 16
    cudaMemsetAsync(pxB, 0, (size_t)NN * 16 * 4, 0);
    k_edge<16, 16><<<EG, TB>>>((const float*)pxA, w[3], src, dst, ea);
    cudaMemsetAsync(pstats, 0, 64 * 4, 0);
    k_div_stats<16><<<592, TB>>>();
    k_bn<16><<<592, TB>>>(gm[3], bt[3]);

    // conv5: 16 -> 32
    cudaMemsetAsync(pxB, 0, (size_t)NN * 32 * 4, 0);
    k_edge<16, 32><<<EG, TB>>>((const float*)pxA, w[4], src, dst, ea);
    cudaMemsetAsync(pstats, 0, 64 * 4, 0);
    k_div_stats<32><<<592, TB>>>();
    k_bn<32><<<592, TB>>>(gm[4], bt[4]);

    // ---- MaxPooling (voxel grid) ----
    cudaMemsetAsync(pxp, 0, (size_t)MM * 32 * 4, 0);
    cudaMemsetAsync(ppp, 0, (size_t)MM * 3 * 4, 0);
    cudaMemsetAsync(pcnt, 0, (size_t)MM * 4, 0);
    cudaMemsetAsync(padj, 0, (size_t)MM * MM, 0);
    cudaMemsetAsync(pmaxv, 0, 4, 0);
    cudaMemsetAsync(pnm, 0, 4, 0);
    cudaMemsetAsync(pxg, 0, (size_t)BB * GRD * 32 * 4, 0);

    k_cluster<<<NG, TB>>>(pos, batch, (const float*)pxA);
    k_ppfin<<<(MM + TB - 1) / TB, TB>>>();
    k_adj<<<EG, TB>>>(src, dst);
    k_maxv<<<592, TB>>>();

    // conv6: 32 -> 32 (pooled)
    k_pz<<<(MM * 256 + TB - 1) / TB, TB>>>((const float*)pxp, w[5]);
    k_pconv<<<MM, 256>>>(d_xt);
    k_pstats<<<1, 1024>>>(d_xt);
    k_pbn<<<(MM * 32 + TB - 1) / TB, TB>>>(d_xt, gm[5], bt[5], (float*)pxu);

    // conv7: 32 -> 32 (pooled)
    k_pz<<<(MM * 256 + TB - 1) / TB, TB>>>((const float*)pxu, w[6]);
    k_pconv<<<MM, 256>>>(d_xt);
    k_pstats<<<1, 1024>>>(d_xt);
    k_pbn<<<(MM * 32 + TB - 1) / TB, TB>>>(d_xt, gm[6], bt[6], (float*)pxu);

    // ---- MaxPoolingX + FC ----
    k_poolX<<<(MM * 32 + TB - 1) / TB, TB>>>((const float*)pxu);
    k_fc<<<BB, 64>>>(fcw, out);
}

// round 3
// speedup vs baseline: 1.0060x; 1.0021x over previous
#include <cuda_runtime.h>
#include <math.h>

#define NN   250000
#define EE   1000000
#define BB   25
#define NX_  8
#define NY_  9
#define NCC  72
#define MM   1800
#define GRD  16
#define NOUTC 2
#define EPSB 1e-5f

// ---------------- scratch (device globals; no allocation allowed) -------------
__device__ float d_xA[NN * 32];          // conv outputs (post BN+relu)
__device__ float d_xB[NN * 32];          // conv accumulators / divided values
__device__ int   d_deg[NN];
__device__ int   d_clu[NN];
__device__ float d_stats[64];            // [sum(Cout), sumsq(Cout)]
__device__ float d_xp[MM * 32];          // pooled features (max pooled)
__device__ float d_pp[MM * 3];           // pooled positions
__device__ int   d_cnt[MM];
__device__ unsigned char d_adj[MM * MM];
__device__ int   d_maxv;                 // float bits (non-negative)
__device__ int   d_nm;                   // number of non-empty cells
__device__ float d_pz[MM * 8 * 32];      // per-node spline projections
__device__ float d_xt[MM * 32];          // pooled conv raw output
__device__ float d_xu[MM * 32];          // pooled conv post-BN output
__device__ float d_xg[BB * GRD * 32];    // MaxPoolingX output

// ---------------- helpers ----------------------------------------------------
__device__ __forceinline__ void basis8(float p0, float p1, float p2, float* b) {
    p0 = fminf(fmaxf(p0, 0.f), 1.f);
    p1 = fminf(fmaxf(p1, 0.f), 1.f);
    p2 = fminf(fmaxf(p2, 0.f), 1.f);
    float q0 = 1.f - p0, q1 = 1.f - p1, q2 = 1.f - p2;
    b[0] = q0 * q1 * q2; b[1] = p0 * q1 * q2;
    b[2] = q0 * p1 * q2; b[3] = p0 * p1 * q2;
    b[4] = q0 * q1 * p2; b[5] = p0 * q1 * p2;
    b[6] = q0 * p1 * p2; b[7] = p0 * p1 * p2;
}

__device__ __forceinline__ void atomicMaxFloatPos(float* addr, float v) {
    // valid for v >= 0 with 0-initialized destination
    atomicMax(reinterpret_cast<int*>(addr), __float_as_int(v));
}

// ---------------- degree -----------------------------------------------------
__global__ void k_deg(const int* __restrict__ dst) {
    int e = blockIdx.x * blockDim.x + threadIdx.x;
    if (e < EE) atomicAdd(&d_deg[dst[e]], 1);
}

// ---------------- SplineConv edge scatter ------------------------------------
template <int CIN, int COUT>
__global__ void k_edge(const float* __restrict__ xin, const float* __restrict__ W,
                       const int* __restrict__ src, const int* __restrict__ dst,
                       const float* __restrict__ ea) {
    __shared__ float Wsh[8 * CIN * COUT];
    for (int i = threadIdx.x; i < 8 * CIN * COUT; i += blockDim.x) Wsh[i] = W[i];
    __syncthreads();
    int e = blockIdx.x * blockDim.x + threadIdx.x;
    if (e >= EE) return;
    int s = src[e], d = dst[e];
    float bs[8];
    basis8(ea[3 * e + 0], ea[3 * e + 1], ea[3 * e + 2], bs);
    float xs[CIN];
    if constexpr (CIN % 4 == 0) {
        const float4* p = reinterpret_cast<const float4*>(xin + (size_t)s * CIN);
#pragma unroll
        for (int i = 0; i < CIN / 4; i++) {
            float4 v = p[i];
            xs[4 * i + 0] = v.x; xs[4 * i + 1] = v.y;
            xs[4 * i + 2] = v.z; xs[4 * i + 3] = v.w;
        }
    } else {
#pragma unroll
        for (int i = 0; i < CIN; i++) xs[i] = xin[(size_t)s * CIN + i];
    }
    float acc[COUT];
#pragma unroll
    for (int c = 0; c < COUT; c++) acc[c] = 0.f;
#pragma unroll
    for (int k = 0; k < 8; k++) {
#pragma unroll
        for (int ci = 0; ci < CIN; ci++) {
            float t = bs[k] * xs[ci];
            const float* wp = &Wsh[(k * CIN + ci) * COUT];
#pragma unroll
            for (int co = 0; co < COUT; co++) acc[co] += t * wp[co];
        }
    }
    float* op = &d_xB[(size_t)d * COUT];
#pragma unroll
    for (int co = 0; co < COUT; co++) atomicAdd(&op[co], acc[co]);
}

// ---------------- mean-divide + BN stats -------------------------------------
template <int COUT>
__global__ void k_div_stats() {
    const int T = gridDim.x * blockDim.x;
    int t = blockIdx.x * blockDim.x + threadIdx.x;
    const int c = t % COUT;  // constant per thread (T % COUT == 0)
    float sum = 0.f, sq = 0.f;
    for (int i = t; i < NN * COUT; i += T) {
        int n = i / COUT;
        float v = d_xB[i] / fmaxf((float)d_deg[n], 1.f);
        d_xB[i] = v;
        sum += v; sq += v * v;
    }
    __shared__ float ss[COUT], s2[COUT];
    if (threadIdx.x < COUT) { ss[threadIdx.x] = 0.f; s2[threadIdx.x] = 0.f; }
    __syncthreads();
    atomicAdd(&ss[c], sum);
    atomicAdd(&s2[c], sq);
    __syncthreads();
    if (threadIdx.x < COUT) {
        atomicAdd(&d_stats[threadIdx.x], ss[threadIdx.x]);
        atomicAdd(&d_stats[COUT + threadIdx.x], s2[threadIdx.x]);
    }
}

// ---------------- BN finalize + relu -----------------------------------------
template <int COUT>
__global__ void k_bn(const float* __restrict__ g, const float* __restrict__ b) {
    const int T = gridDim.x * blockDim.x;
    int t = blockIdx.x * blockDim.x + threadIdx.x;
    const int c = t % COUT;
    float mean = d_stats[c] * (1.f / NN);
    float var = d_stats[COUT + c] * (1.f / NN) - mean * mean;
    float sc = rsqrtf(var + EPSB) * g[c];
    float sh = b[c] - mean * sc;
    for (int i = t; i < NN * COUT; i += T) {
        float v = d_xB[i] * sc + sh;
        d_xA[i] = fmaxf(v, 0.f);
    }
}

// ---------------- voxel pooling ----------------------------------------------
__global__ void k_cluster(const float* __restrict__ pos, const int* __restrict__ batch,
                          const float* __restrict__ x) {
    int n = blockIdx.x * blockDim.x + threadIdx.x;
    if (n >= NN) return;
    float p0 = pos[3 * n + 0], p1 = pos[3 * n + 1], p2 = pos[3 * n + 2];
    int cx = min(max((int)floorf(p0 / 16.0f), 0), NX_ - 1);
    int cy = min(max((int)floorf(p1 / 12.0f), 0), NY_ - 1);
    int cl = batch[n] * NCC + cy * NX_ + cx;
    d_clu[n] = cl;
    atomicAdd(&d_cnt[cl], 1);
    atomicAdd(&d_pp[cl * 3 + 0], p0);
    atomicAdd(&d_pp[cl * 3 + 1], p1);
    atomicAdd(&d_pp[cl * 3 + 2], p2);
    const float4* xr = reinterpret_cast<const float4*>(x + (size_t)n * 32);
#pragma unroll
    for (int i = 0; i < 8; i++) {
        float4 v = xr[i];
        atomicMaxFloatPos(&d_xp[cl * 32 + 4 * i + 0], v.x);
        atomicMaxFloatPos(&d_xp[cl * 32 + 4 * i + 1], v.y);
        atomicMaxFloatPos(&d_xp[cl * 32 + 4 * i + 2], v.z);
        atomicMaxFloatPos(&d_xp[cl * 32 + 4 * i + 3], v.w);
    }
}

__global__ void k_ppfin() {
    int m = blockIdx.x * blockDim.x + threadIdx.x;
    if (m >= MM) return;
    float c = fmaxf((float)d_cnt[m], 1.f);
    d_pp[m * 3 + 0] /= c;
    d_pp[m * 3 + 1] /= c;
    d_pp[m * 3 + 2] /= c;
    if (d_cnt[m] > 0) atomicAdd(&d_nm, 1);
}

__global__ void k_adj(const int* __restrict__ src, const int* __restrict__ dst) {
    int e = blockIdx.x * blockDim.x + threadIdx.x;
    if (e >= EE) return;
    int a = d_clu[src[e]], b = d_clu[dst[e]];
    if (a != b) d_adj[a * MM + b] = 1;
}

__global__ void k_maxv() {
    const int T = gridDim.x * blockDim.x;
    int t = blockIdx.x * blockDim.x + threadIdx.x;
    float mx = 0.f;
    for (int p = t; p < MM * MM; p += T) {
        if (d_adj[p]) {
            int r = p / MM, c = p % MM;
            mx = fmaxf(mx, fabsf(d_pp[c * 3 + 0] - d_pp[r * 3 + 0]));
            mx = fmaxf(mx, fabsf(d_pp[c * 3 + 1] - d_pp[r * 3 + 1]));
            mx = fmaxf(mx, fabsf(d_pp[c * 3 + 2] - d_pp[r * 3 + 2]));
        }
    }
    __shared__ float red[256];
    red[threadIdx.x] = mx;
    __syncthreads();
    for (int o = 128; o > 0; o >>= 1) {
        if (threadIdx.x < o) red[threadIdx.x] = fmaxf(red[threadIdx.x], red[threadIdx.x + o]);
        __syncthreads();
    }
    if (threadIdx.x == 0) atomicMax(&d_maxv, __float_as_int(red[0]));
}

// ---------------- pooled conv: per-node projections z = x . W[s] --------------
__global__ void k_pz(const float* __restrict__ xin, const float* __restrict__ W) {
    int t = blockIdx.x * blockDim.x + threadIdx.x;
    if (t >= MM * 8 * 32) return;
    int co = t & 31;
    int s = (t >> 5) & 7;
    int r = t >> 8;
    float acc = 0.f;
    const float* xr = &xin[r * 32];
    const float* wp = &W[s * 32 * 32 + co];
#pragma unroll
    for (int ci = 0; ci < 32; ci++) acc += xr[ci] * wp[ci * 32];
    d_pz[t] = acc;
}

// ---------------- pooled conv: per-dst aggregation ---------------------------
__global__ void k_pconv(float* __restrict__ out) {
    int c = blockIdx.x;
    int lane = threadIdx.x & 31;
    int w = threadIdx.x >> 5;  // 8 warps
    int g = c / NCC;
    int base = g * NCC;
    float inv = 0.5f / fmaxf(__int_as_float(d_maxv), 1e-9f);
    float pc0 = d_pp[c * 3 + 0], pc1 = d_pp[c * 3 + 1], pc2 = d_pp[c * 3 + 2];
    float acc = 0.f;
    int cnt = 0;
    for (int r = base + w; r < base + NCC; r += 8) {
        if (r == c || !d_adj[r * MM + c]) continue;
        cnt++;
        float bs[8];
        basis8((pc0 - d_pp[r * 3 + 0]) * inv + 0.5f,
               (pc1 - d_pp[r * 3 + 1]) * inv + 0.5f,
               (pc2 - d_pp[r * 3 + 2]) * inv + 0.5f, bs);
        const float* z = &d_pz[r * 256];
#pragma unroll
        for (int s = 0; s < 8; s++) acc += bs[s] * z[s * 32 + lane];
    }
    __shared__ float sa[8][32];
    __shared__ int scn[8];
    sa[w][lane] = acc;
    if (lane == 0) scn[w] = cnt;
    __syncthreads();
    if (w == 0) {
        float a = 0.f;
        int k = 0;
#pragma unroll
        for (int j = 0; j < 8; j++) { a += sa[j][lane]; k += scn[j]; }
        out[c * 32 + lane] = a / fmaxf((float)k, 1.f);
    }
}

// ---------------- pooled (masked) BN stats + finalize ------------------------
__global__ void k_pstats(const float* __restrict__ x) {
    int tid = threadIdx.x;  // one block, 1024 threads
    const int c = tid & 31;
    float sum = 0.f, sq = 0.f;
    for (int i = tid; i < MM * 32; i += 1024) {
        if (d_cnt[i >> 5] > 0) {
            float v = x[i];
            sum += v; sq += v * v;
        }
    }
    __shared__ float ss[32], s2[32];
    if (tid < 32) { ss[tid] = 0.f; s2[tid] = 0.f; }
    __syncthreads();
    atomicAdd(&ss[c], sum);
    atomicAdd(&s2[c], sq);
    __syncthreads();
    if (tid < 32) { d_stats[tid] = ss[tid]; d_stats[32 + tid] = s2[tid]; }
}

__global__ void k_pbn(const float* __restrict__ x, const float* __restrict__ g,
                      const float* __restrict__ b, float* __restrict__ out) {
    int i = blockIdx.x * blockDim.x + threadIdx.x;
    if (i >= MM * 32) return;
    int c = i & 31;
    float cntf = fmaxf((float)d_nm, 1.f);
    float mean = d_stats[c] / cntf;
    float var = d_stats[32 + c] / cntf - mean * mean;
    float v = (x[i] - mean) * rsqrtf(var + EPSB) * g[c] + b[c];
    if (d_cnt[i >> 5] <= 0) v = 0.f;
    out[i] = fmaxf(v, 0.f);
}

// ---------------- MaxPoolingX + FC -------------------------------------------
__global__ void k_poolX(const float* __restrict__ x) {
    int i = blockIdx.x * blockDim.x + threadIdx.x;
    if (i >= MM * 32) return;
    int m = i >> 5, ch = i & 31;
    if (d_cnt[m] <= 0) return;
    int g = m / NCC;
    int gx = min(max((int)floorf(d_pp[m * 3 + 0] / 30.0f), 0), 3);
    int gy = min(max((int)floorf(d_pp[m * 3 + 1] / 25.0f), 0), 3);
    int seg = g * GRD + gy * 4 + gx;
    atomicMaxFloatPos(&d_xg[seg * 32 + ch], x[i]);
}

__global__ void k_fc(const float* __restrict__ fcw, float* __restrict__ out) {
    int b = blockIdx.x;            // BB blocks
    int o = threadIdx.x >> 5;      // 2 warps
    int lane = threadIdx.x & 31;
    float s = 0.f;
    for (int j = lane; j < GRD * 32; j += 32)
        s += d_xg[b * GRD * 32 + j] * fcw[o * GRD * 32 + j];
#pragma unroll
    for (int off = 16; off; off >>= 1) s += __shfl_down_sync(0xffffffff, s, off);
    if (lane == 0) out[b * NOUTC + o] = s;
}

// ---------------- host orchestration -----------------------------------------
extern "C" void kernel_launch(void* const* d_in, const int* in_sizes, int n_in,
                              void* d_out, int out_size) {
    const float* x   = (const float*)d_in[0];
    const float* pos = (const float*)d_in[1];
    const float* ea  = (const float*)d_in[2];
    const float* w[7];
    const float* gm[7];
    const float* bt[7];
    for (int i = 0; i < 7; i++) {
        w[i]  = (const float*)d_in[3 + i];
        gm[i] = (const float*)d_in[10 + i];
        bt[i] = (const float*)d_in[17 + i];
    }
    const float* fcw = (const float*)d_in[24];
    const int* ei    = (const int*)d_in[25];
    const int* batch = (const int*)d_in[26];
    const int* src = ei;
    const int* dst = ei + EE;
    float* out = (float*)d_out;

    void *pxA, *pxB, *pdeg, *pstats, *pxp, *ppp, *pcnt, *padj, *pmaxv, *pnm, *pxg, *pxu;
    cudaGetSymbolAddress(&pxA, d_xA);
    cudaGetSymbolAddress(&pxB, d_xB);
    cudaGetSymbolAddress(&pdeg, d_deg);
    cudaGetSymbolAddress(&pstats, d_stats);
    cudaGetSymbolAddress(&pxp, d_xp);
    cudaGetSymbolAddress(&ppp, d_pp);
    cudaGetSymbolAddress(&pcnt, d_cnt);
    cudaGetSymbolAddress(&padj, d_adj);
    cudaGetSymbolAddress(&pmaxv, d_maxv);
    cudaGetSymbolAddress(&pnm, d_nm);
    cudaGetSymbolAddress(&pxg, d_xg);
    cudaGetSymbolAddress(&pxu, d_xu);

    const int TB = 256;
    const int EG = (EE + TB - 1) / TB;
    const int NG = (NN + TB - 1) / TB;

    cudaMemsetAsync(pdeg, 0, (size_t)NN * 4, 0);
    k_deg<<<EG, TB>>>(dst);

    // conv1: 1 -> 8
    cudaMemsetAsync(pxB, 0, (size_t)NN * 8 * 4, 0);
    k_edge<1, 8><<<EG, TB>>>(x, w[0], src, dst, ea);
    cudaMemsetAsync(pstats, 0, 64 * 4, 0);
    k_div_stats<8><<<592, TB>>>();
    k_bn<8><<<592, TB>>>(gm[0], bt[0]);

    // conv2: 8 -> 16
    cudaMemsetAsync(pxB, 0, (size_t)NN * 16 * 4, 0);
    k_edge<8, 16><<<EG, TB>>>((const float*)pxA, w[1], src, dst, ea);
    cudaMemsetAsync(pstats, 0, 64 * 4, 0);
    k_div_stats<16><<<592, TB>>>();
    k_bn<16><<<592, TB>>>(gm[1], bt[1]);

    // conv3: 16 -> 16
    cudaMemsetAsync(pxB, 0, (size_t)NN * 16 * 4, 0);
    k_edge<16, 16><<<EG, TB>>>((const float*)pxA, w[2], src, dst, ea);
    cudaMemsetAsync(pstats, 0, 64 * 4, 0);
    k_div_stats<16><<<592, TB>>>();
    k_bn<16><<<592, TB>>>(gm[2], bt[2]);

    // conv4: 16 -> 16
    cudaMemsetAsync(pxB, 0, (size_t)NN * 16 * 4, 0);
    k_edge<16, 16><<<EG, TB>>>((const float*)pxA, w[3], src, dst, ea);
    cudaMemsetAsync(pstats, 0, 64 * 4, 0);
    k_div_stats<16><<<592, TB>>>();
    k_bn<16><<<592, TB>>>(gm[3], bt[3]);

    // conv5: 16 -> 32
    cudaMemsetAsync(pxB, 0, (size_t)NN * 32 * 4, 0);
    k_edge<16, 32><<<EG, TB>>>((const float*)pxA, w[4], src, dst, ea);
    cudaMemsetAsync(pstats, 0, 64 * 4, 0);
    k_div_stats<32><<<592, TB>>>();
    k_bn<32><<<592, TB>>>(gm[4], bt[4]);

    // ---- MaxPooling (voxel grid) ----
    cudaMemsetAsync(pxp, 0, (size_t)MM * 32 * 4, 0);
    cudaMemsetAsync(ppp, 0, (size_t)MM * 3 * 4, 0);
    cudaMemsetAsync(pcnt, 0, (size_t)MM * 4, 0);
    cudaMemsetAsync(padj, 0, (size_t)MM * MM, 0);
    cudaMemsetAsync(pmaxv, 0, 4, 0);
    cudaMemsetAsync(pnm, 0, 4, 0);
    cudaMemsetAsync(pxg, 0, (size_t)BB * GRD * 32 * 4, 0);

    k_cluster<<<NG, TB>>>(pos, batch, (const float*)pxA);
    k_ppfin<<<(MM + TB - 1) / TB, TB>>>();
    k_adj<<<EG, TB>>>(src, dst);
    k_maxv<<<592, TB>>>();

    // conv6: 32 -> 32 (pooled)
    k_pz<<<(MM * 256 + TB - 1) / TB, TB>>>((const float*)pxp, w[5]);
    k_pconv<<<MM, 256>>>(d_xt);
    k_pstats<<<1, 1024>>>(d_xt);
    k_pbn<<<(MM * 32 + TB - 1) / TB, TB>>>(d_xt, gm[5], bt[5], (float*)pxu);

    // conv7: 32 -> 32 (pooled)
    k_pz<<<(MM * 256 + TB - 1) / TB, TB>>>((const float*)pxu, w[6]);
    k_pconv<<<MM, 256>>>(d_xt);
    k_pstats<<<1, 1024>>>(d_xt);
    k_pbn<<<(MM * 32 + TB - 1) / TB, TB>>>(d_xt, gm[6], bt[6], (float*)pxu);

    // ---- MaxPoolingX + FC ----
    k_poolX<<<(MM * 32 + TB - 1) / TB, TB>>>((const float*)pxu);
    k_fc<<<BB, 64>>>(fcw, out);
}